// round 1
// baseline (speedup 1.0000x reference)
#include <cuda_runtime.h>
#include <math.h>

#define Bn 16
#define Tn 512
#define Cn 256
#define Hn 8
#define FFn 1024
#define LNEPS 1e-6f

#define SZ_BTC (Bn*Tn*Cn)     /* 2,097,152 */
#define SZ_FFH (Bn*Tn*FFn)    /* 8,388,608 */

// scratch offsets (floats)
#define OFF_H    0
#define OFF_Q    (SZ_BTC*1)
#define OFF_K    (SZ_BTC*2)
#define OFF_V    (SZ_BTC*3)
#define OFF_O    (SZ_BTC*4)
#define OFF_X    (SZ_BTC*5)
#define OFF_TOUT (SZ_BTC*6)
#define OFF_HS   (SZ_BTC*7)
#define OFF_QS   (SZ_BTC*8)
#define OFF_KS   (SZ_BTC*9)
#define OFF_X2   (SZ_BTC*10)
#define OFF_FFH  (SZ_BTC*11)
#define OFF_SC   OFF_FFH      /* sc consumed before FFN2 reuses this region */
#define TOTAL_SCRATCH (SZ_BTC*11 + SZ_FFH)

__device__ float g_scratch[TOTAL_SCRATCH];

// ---------------------------------------------------------------------------
// LayerNorm over last dim N (row per block, 256 threads)
// ---------------------------------------------------------------------------
__global__ __launch_bounds__(256) void ln_kernel(
    const float* __restrict__ x, const float* __restrict__ w,
    const float* __restrict__ b, float* __restrict__ out, int N)
{
    int row = blockIdx.x;
    const float* xr = x + (size_t)row * N;
    float* orow = out + (size_t)row * N;
    __shared__ float red[256];
    int tid = threadIdx.x;

    float s = 0.f;
    for (int i = tid; i < N; i += 256) s += xr[i];
    red[tid] = s; __syncthreads();
    for (int off = 128; off > 0; off >>= 1) {
        if (tid < off) red[tid] += red[tid + off];
        __syncthreads();
    }
    float mean = red[0] / N;
    __syncthreads();

    float v = 0.f;
    for (int i = tid; i < N; i += 256) { float d = xr[i] - mean; v += d * d; }
    red[tid] = v; __syncthreads();
    for (int off = 128; off > 0; off >>= 1) {
        if (tid < off) red[tid] += red[tid + off];
        __syncthreads();
    }
    float rstd = rsqrtf(red[0] / N + LNEPS);

    for (int i = tid; i < N; i += 256)
        orow[i] = (xr[i] - mean) * rstd * w[i] + b[i];
}

// ---------------------------------------------------------------------------
// Generic GEMM: C[m,n] = alpha * sum_k A[m,k]*B[n,k]  (+bias[n]) (relu) (+res)
// Tiles 64x64, BK=16, 256 threads, 4x4 per thread. Batched via grid.z:
//   aOff = (z/hd)*zAo + (z%hd)*zAi (same form for B); C/res offset z*zC / z*zR.
// Requires M%64==0, N%64==0, K%16==0 (true for every call here).
// ---------------------------------------------------------------------------
__global__ __launch_bounds__(256) void gemm_nt(
    const float* __restrict__ A, int lda,
    const float* __restrict__ Bp, int ldb,
    float* __restrict__ Cp, int ldc,
    const float* __restrict__ bias,
    const float* __restrict__ res,
    int K, float alpha, int doRelu,
    long long zAo, long long zAi, long long zBo, long long zBi,
    long long zC, long long zR, int hd)
{
    int z = blockIdx.z;
    long long aOff = (long long)(z / hd) * zAo + (long long)(z % hd) * zAi;
    long long bOff = (long long)(z / hd) * zBo + (long long)(z % hd) * zBi;
    A  += aOff;
    Bp += bOff;
    Cp += (long long)z * zC;
    if (res) res += (long long)z * zR;

    __shared__ float As[16][64];
    __shared__ float Bs[16][64];

    int tx = threadIdx.x & 15;
    int ty = threadIdx.x >> 4;
    int m0 = blockIdx.y * 64;
    int n0 = blockIdx.x * 64;

    float acc[4][4] = {};

    int lr = threadIdx.x >> 2;          // 0..63 row within tile
    int lk = (threadIdx.x & 3) * 4;     // 0,4,8,12 k-group

    for (int k0 = 0; k0 < K; k0 += 16) {
        float4 av = *(const float4*)(A  + (size_t)(m0 + lr) * lda + k0 + lk);
        float4 bv = *(const float4*)(Bp + (size_t)(n0 + lr) * ldb + k0 + lk);
        As[lk + 0][lr] = av.x; As[lk + 1][lr] = av.y;
        As[lk + 2][lr] = av.z; As[lk + 3][lr] = av.w;
        Bs[lk + 0][lr] = bv.x; Bs[lk + 1][lr] = bv.y;
        Bs[lk + 2][lr] = bv.z; Bs[lk + 3][lr] = bv.w;
        __syncthreads();

        #pragma unroll
        for (int k = 0; k < 16; k++) {
            float4 a4 = *(const float4*)&As[k][ty * 4];
            float4 b4 = *(const float4*)&Bs[k][tx * 4];
            acc[0][0] += a4.x * b4.x; acc[0][1] += a4.x * b4.y;
            acc[0][2] += a4.x * b4.z; acc[0][3] += a4.x * b4.w;
            acc[1][0] += a4.y * b4.x; acc[1][1] += a4.y * b4.y;
            acc[1][2] += a4.y * b4.z; acc[1][3] += a4.y * b4.w;
            acc[2][0] += a4.z * b4.x; acc[2][1] += a4.z * b4.y;
            acc[2][2] += a4.z * b4.z; acc[2][3] += a4.z * b4.w;
            acc[3][0] += a4.w * b4.x; acc[3][1] += a4.w * b4.y;
            acc[3][2] += a4.w * b4.z; acc[3][3] += a4.w * b4.w;
        }
        __syncthreads();
    }

    #pragma unroll
    for (int i = 0; i < 4; i++) {
        int m = m0 + ty * 4 + i;
        #pragma unroll
        for (int j = 0; j < 4; j++) {
            int n = n0 + tx * 4 + j;
            float v = acc[i][j] * alpha;
            if (bias) v += bias[n];
            if (doRelu) v = fmaxf(v, 0.f);
            size_t ci = (size_t)m * ldc + n;
            if (res) v += res[ci];
            Cp[ci] = v;
        }
    }
}

// ---------------------------------------------------------------------------
// Temporal causal attention. One block per (b,h). K,V fully resident in smem.
// 8 warps; warp w processes query tiles w and 15-w (load balance: 17 key-tiles
// each). Lane owns one query row; register-resident online softmax.
// q is pre-scaled by 1/sqrt(32) in the q projection GEMM.
// ---------------------------------------------------------------------------
__global__ __launch_bounds__(256) void attn_t_kernel(
    const float* __restrict__ q, const float* __restrict__ k,
    const float* __restrict__ v, float* __restrict__ o)
{
    extern __shared__ float smem[];
    float4* Ks = (float4*)smem;             // [Tn][8] float4
    float4* Vs = (float4*)(smem + Tn * 32); // [Tn][8] float4

    int bh = blockIdx.x;
    int b = bh / Hn, h = bh % Hn;
    const size_t base = (size_t)b * Tn * Cn + (size_t)h * 32;

    for (int i = threadIdx.x; i < Tn * 8; i += 256) {
        int s = i >> 3, d4 = i & 7;
        Ks[i] = *(const float4*)(k + base + (size_t)s * Cn + d4 * 4);
        Vs[i] = *(const float4*)(v + base + (size_t)s * Cn + d4 * 4);
    }
    __syncthreads();

    int warp = threadIdx.x >> 5;
    int lane = threadIdx.x & 31;

    for (int pass = 0; pass < 2; pass++) {
        int qt = (pass == 0) ? warp : (15 - warp);
        int t = qt * 32 + lane;

        float qr[32];
        #pragma unroll
        for (int d4 = 0; d4 < 8; d4++) {
            float4 qv = *(const float4*)(q + base + (size_t)t * Cn + d4 * 4);
            qr[d4 * 4 + 0] = qv.x; qr[d4 * 4 + 1] = qv.y;
            qr[d4 * 4 + 2] = qv.z; qr[d4 * 4 + 3] = qv.w;
        }

        float m = -INFINITY, l = 0.f;
        float oa[32];
        #pragma unroll
        for (int d = 0; d < 32; d++) oa[d] = 0.f;

        for (int st = 0; st <= qt; st++) {
            float sc[32];
            float mx = -INFINITY;
            #pragma unroll
            for (int sk = 0; sk < 32; sk++) {
                int s = st * 32 + sk;
                float a = 0.f;
                #pragma unroll
                for (int d4 = 0; d4 < 8; d4++) {
                    float4 kk = Ks[s * 8 + d4];
                    a += qr[d4 * 4 + 0] * kk.x + qr[d4 * 4 + 1] * kk.y
                       + qr[d4 * 4 + 2] * kk.z + qr[d4 * 4 + 3] * kk.w;
                }
                if (st == qt && sk > lane) a = -INFINITY;
                sc[sk] = a;
                mx = fmaxf(mx, a);
            }
            float mn = fmaxf(m, mx);
            float f = expf(m - mn);      // first iter: exp(-inf)=0
            l *= f;
            #pragma unroll
            for (int d = 0; d < 32; d++) oa[d] *= f;

            #pragma unroll
            for (int sk = 0; sk < 32; sk++) {
                float p = expf(sc[sk] - mn);  // masked: exp(-inf)=0
                l += p;
                int s = st * 32 + sk;
                #pragma unroll
                for (int d4 = 0; d4 < 8; d4++) {
                    float4 vv = Vs[s * 8 + d4];
                    oa[d4 * 4 + 0] += p * vv.x; oa[d4 * 4 + 1] += p * vv.y;
                    oa[d4 * 4 + 2] += p * vv.z; oa[d4 * 4 + 3] += p * vv.w;
                }
            }
            m = mn;
        }

        float inv = 1.f / l;
        #pragma unroll
        for (int d4 = 0; d4 < 8; d4++) {
            float4 w4;
            w4.x = oa[d4 * 4 + 0] * inv; w4.y = oa[d4 * 4 + 1] * inv;
            w4.z = oa[d4 * 4 + 2] * inv; w4.w = oa[d4 * 4 + 3] * inv;
            *(float4*)(o + base + (size_t)t * Cn + d4 * 4) = w4;
        }
    }
}

// ---------------------------------------------------------------------------
// Spatial: per (b,c) row, softmax over e for each head, mean over heads.
// sc layout: [B,H,C,C]. Output sw [B,C,C]. 256 threads = one e per thread.
// ---------------------------------------------------------------------------
__global__ __launch_bounds__(256) void softmax_mean_kernel(
    const float* __restrict__ sc, float* __restrict__ sw)
{
    int bc = blockIdx.x;
    int b = bc / Cn, c = bc % Cn;
    int e = threadIdx.x;
    __shared__ float red[256];

    float acc = 0.f;
    for (int h = 0; h < Hn; h++) {
        float s = sc[(((size_t)(b * Hn + h) * Cn) + c) * Cn + e];
        red[e] = s; __syncthreads();
        for (int off = 128; off > 0; off >>= 1) {
            if (e < off) red[e] = fmaxf(red[e], red[e + off]);
            __syncthreads();
        }
        float mx = red[0]; __syncthreads();
        float p = expf(s - mx);
        red[e] = p; __syncthreads();
        for (int off = 128; off > 0; off >>= 1) {
            if (e < off) red[e] += red[e + off];
            __syncthreads();
        }
        acc += p / red[0];
        __syncthreads();
    }
    sw[(size_t)bc * Cn + e] = acc * (1.f / Hn);
}

// ---------------------------------------------------------------------------
// Host side
// ---------------------------------------------------------------------------
static void launch_gemm(const float* A, int lda, const float* Bp, int ldb,
                        float* Cp, int ldc, const float* bias, const float* res,
                        int M, int N, int K, float alpha, int doRelu,
                        int nz = 1,
                        long long zAo = 0, long long zAi = 0,
                        long long zBo = 0, long long zBi = 0,
                        long long zC = 0, long long zR = 0, int hd = 1)
{
    dim3 g(N / 64, M / 64, nz), blk(256);
    gemm_nt<<<g, blk>>>(A, lda, Bp, ldb, Cp, ldc, bias, res, K, alpha, doRelu,
                        zAo, zAi, zBo, zBi, zC, zR, hd);
}

extern "C" void kernel_launch(void* const* d_in, const int* in_sizes, int n_in,
                              void* d_out, int out_size)
{
    const float* x_T     = (const float*)d_in[0];
    const float* x_S     = (const float*)d_in[1];
    const float* Wq_t    = (const float*)d_in[2];
    const float* Wk_t    = (const float*)d_in[3];
    const float* Wv_t    = (const float*)d_in[4];
    const float* Wo      = (const float*)d_in[5];
    const float* Wq_s    = (const float*)d_in[6];
    const float* Wk_s    = (const float*)d_in[7];
    const float* ff1_w1  = (const float*)d_in[8];
    const float* ff1_b1  = (const float*)d_in[9];
    const float* ff1_w2  = (const float*)d_in[10];
    const float* ff1_b2  = (const float*)d_in[11];
    const float* ff2_w1  = (const float*)d_in[12];
    const float* ff2_b1  = (const float*)d_in[13];
    const float* ff2_w2  = (const float*)d_in[14];
    const float* ff2_b2  = (const float*)d_in[15];
    const float* t_ln1_w = (const float*)d_in[16];
    const float* t_ln1_b = (const float*)d_in[17];
    const float* t_ln2_w = (const float*)d_in[18];
    const float* t_ln2_b = (const float*)d_in[19];
    const float* s_ln1_w = (const float*)d_in[20];
    const float* s_ln1_b = (const float*)d_in[21];
    const float* fus_ln_w = (const float*)d_in[22];
    const float* fus_ln_b = (const float*)d_in[23];

    float* S = nullptr;
    cudaGetSymbolAddress((void**)&S, g_scratch);

    float* out = (float*)d_out;            // [B,T,C]
    float* sw  = out + SZ_BTC;             // [B,C,C] spatial_weights

    cudaFuncSetAttribute(attn_t_kernel,
                         cudaFuncAttributeMaxDynamicSharedMemorySize, 131072);

    const float iq = 0.17677669529663687f;  // 1/sqrt(32)

    // ---- temporal branch ----
    ln_kernel<<<Bn * Tn, 256>>>(x_T, t_ln1_w, t_ln1_b, S + OFF_H, Cn);
    launch_gemm(S + OFF_H, Cn, Wq_t, Cn, S + OFF_Q, Cn, nullptr, nullptr,
                Bn * Tn, Cn, Cn, iq, 0);
    launch_gemm(S + OFF_H, Cn, Wk_t, Cn, S + OFF_K, Cn, nullptr, nullptr,
                Bn * Tn, Cn, Cn, 1.f, 0);
    launch_gemm(S + OFF_H, Cn, Wv_t, Cn, S + OFF_V, Cn, nullptr, nullptr,
                Bn * Tn, Cn, Cn, 1.f, 0);
    attn_t_kernel<<<Bn * Hn, 256, 131072>>>(S + OFF_Q, S + OFF_K, S + OFF_V,
                                            S + OFF_O);
    launch_gemm(S + OFF_O, Cn, Wo, Cn, S + OFF_X, Cn, nullptr, x_T,
                Bn * Tn, Cn, Cn, 1.f, 0);
    ln_kernel<<<Bn * Tn, 256>>>(S + OFF_X, t_ln2_w, t_ln2_b, S + OFF_H, Cn);
    launch_gemm(S + OFF_H, Cn, ff1_w1, Cn, S + OFF_FFH, FFn, ff1_b1, nullptr,
                Bn * Tn, FFn, Cn, 1.f, 1);
    launch_gemm(S + OFF_FFH, FFn, ff1_w2, FFn, S + OFF_TOUT, Cn, ff1_b2,
                S + OFF_X, Bn * Tn, Cn, FFn, 1.f, 0);

    // ---- spatial branch ----
    ln_kernel<<<Bn * Cn, 256>>>(x_S, s_ln1_w, s_ln1_b, S + OFF_HS, Tn);
    launch_gemm(S + OFF_HS, Tn, Wq_s, Tn, S + OFF_QS, Hn * 64, nullptr, nullptr,
                Bn * Cn, Hn * 64, Tn, 1.f, 0);
    launch_gemm(S + OFF_HS, Tn, Wk_s, Tn, S + OFF_KS, Hn * 64, nullptr, nullptr,
                Bn * Cn, Hn * 64, Tn, 1.f, 0);
    // sc[b,h] = 0.125 * qs_bh @ ks_bh^T   (batched over z = b*H + h)
    launch_gemm(S + OFF_QS, Hn * 64, S + OFF_KS, Hn * 64, S + OFF_SC, Cn,
                nullptr, nullptr, Cn, Cn, 64, 0.125f, 0,
                Bn * Hn,
                (long long)Cn * (Hn * 64), 64,
                (long long)Cn * (Hn * 64), 64,
                (long long)Cn * Cn, 0, Hn);
    softmax_mean_kernel<<<Bn * Cn, 256>>>(S + OFF_SC, sw);

    // ---- fusion: x2 = tout + tout @ sw^T  (batched over b) ----
    launch_gemm(S + OFF_TOUT, Cn, sw, Cn, S + OFF_X2, Cn, nullptr,
                S + OFF_TOUT, Tn, Cn, Cn, 1.f, 0,
                Bn,
                (long long)Tn * Cn, 0,
                (long long)Cn * Cn, 0,
                (long long)Tn * Cn, (long long)Tn * Cn, 1);

    // ---- FFN2 -> out ----
    ln_kernel<<<Bn * Tn, 256>>>(S + OFF_X2, fus_ln_w, fus_ln_b, S + OFF_H, Cn);
    launch_gemm(S + OFF_H, Cn, ff2_w1, Cn, S + OFF_FFH, FFn, ff2_b1, nullptr,
                Bn * Tn, FFn, Cn, 1.f, 1);
    launch_gemm(S + OFF_FFH, FFn, ff2_w2, FFn, out, Cn, ff2_b2, S + OFF_X2,
                Bn * Tn, Cn, FFn, 1.f, 0);
}

// round 2
// speedup vs baseline: 1.2074x; 1.2074x over previous
#include <cuda_runtime.h>
#include <math.h>

#define Bn 16
#define Tn 512
#define Cn 256
#define Hn 8
#define FFn 1024
#define LNEPS 1e-6f

#define SZ_BTC (Bn*Tn*Cn)     /* 2,097,152 */
#define SZ_FFH (Bn*Tn*FFn)    /* 8,388,608 */

// scratch offsets (floats)
#define OFF_H    0
#define OFF_Q    (SZ_BTC*1)
#define OFF_K    (SZ_BTC*2)
#define OFF_V    (SZ_BTC*3)
#define OFF_O    (SZ_BTC*4)
#define OFF_X    (SZ_BTC*5)
#define OFF_TOUT (SZ_BTC*6)
#define OFF_HS   (SZ_BTC*7)
#define OFF_QS   (SZ_BTC*8)
#define OFF_KS   (SZ_BTC*9)
#define OFF_X2   (SZ_BTC*10)
#define OFF_FFH  (SZ_BTC*11)
#define OFF_SC   OFF_FFH      /* sc consumed before FFN2 reuses this region */
#define TOTAL_SCRATCH (SZ_BTC*11 + SZ_FFH)

__device__ float g_scratch[TOTAL_SCRATCH];

// ---------------------------------------------------------------------------
// LayerNorm over last dim N (row per block, 256 threads)
// ---------------------------------------------------------------------------
__global__ __launch_bounds__(256) void ln_kernel(
    const float* __restrict__ x, const float* __restrict__ w,
    const float* __restrict__ b, float* __restrict__ out, int N)
{
    int row = blockIdx.x;
    const float* xr = x + (size_t)row * N;
    float* orow = out + (size_t)row * N;
    __shared__ float red[256];
    int tid = threadIdx.x;

    float s = 0.f;
    for (int i = tid; i < N; i += 256) s += xr[i];
    red[tid] = s; __syncthreads();
    for (int off = 128; off > 0; off >>= 1) {
        if (tid < off) red[tid] += red[tid + off];
        __syncthreads();
    }
    float mean = red[0] / N;
    __syncthreads();

    float v = 0.f;
    for (int i = tid; i < N; i += 256) { float d = xr[i] - mean; v += d * d; }
    red[tid] = v; __syncthreads();
    for (int off = 128; off > 0; off >>= 1) {
        if (tid < off) red[tid] += red[tid + off];
        __syncthreads();
    }
    float rstd = rsqrtf(red[0] / N + LNEPS);

    for (int i = tid; i < N; i += 256)
        orow[i] = (xr[i] - mean) * rstd * w[i] + b[i];
}

// ---------------------------------------------------------------------------
// GEMM: C[m,n] = alpha * sum_k A[m,k]*B[n,k]  (+bias[n]) (relu) (+res)
// 128x128 tile, BK=8, 256 threads, 8x8 per thread, double-buffered smem,
// register-prefetch gmem. Batched via grid.z:
//   aOff = (z/hd)*zAo + (z%hd)*zAi (same form for B); C/res offset z*zC/z*zR.
// Requires M%128==0, N%128==0, K%8==0 (true for every call here).
// ---------------------------------------------------------------------------
__global__ __launch_bounds__(256, 2) void gemm_nt(
    const float* __restrict__ A, int lda,
    const float* __restrict__ Bp, int ldb,
    float* __restrict__ Cp, int ldc,
    const float* __restrict__ bias,
    const float* __restrict__ res,
    int K, float alpha, int doRelu,
    long long zAo, long long zAi, long long zBo, long long zBi,
    long long zC, long long zR, int hd)
{
    int z = blockIdx.z;
    long long aOff = (long long)(z / hd) * zAo + (long long)(z % hd) * zAi;
    long long bOff = (long long)(z / hd) * zBo + (long long)(z % hd) * zBi;
    A  += aOff;
    Bp += bOff;
    Cp += (long long)z * zC;
    if (res) res += (long long)z * zR;

    __shared__ float As[2][8][132];
    __shared__ float Bs[2][8][132];

    int tid  = threadIdx.x;
    int m0   = blockIdx.y * 128;
    int n0   = blockIdx.x * 128;

    int warp = tid >> 5, lane = tid & 31;
    int warpY = warp >> 1, warpX = warp & 1;     // 4 x 2 warps
    int ly = lane >> 3, lx = lane & 7;           // 4 x 8 lanes
    int rowBase = warpY * 32 + ly * 8;           // this thread's 8 rows
    int colBase = warpX * 64 + lx * 8;           // this thread's 8 cols

    int ldRow = tid >> 1;                        // 0..127
    int ldK   = (tid & 1) * 4;                   // 0 or 4

    const float* Aptr = A  + (size_t)(m0 + ldRow) * lda + ldK;
    const float* Bptr = Bp + (size_t)(n0 + ldRow) * ldb + ldK;

    float acc[8][8] = {};

    // preload k-tile 0
    float4 aF = *(const float4*)Aptr;
    float4 bF = *(const float4*)Bptr;
    As[0][ldK + 0][ldRow] = aF.x; As[0][ldK + 1][ldRow] = aF.y;
    As[0][ldK + 2][ldRow] = aF.z; As[0][ldK + 3][ldRow] = aF.w;
    Bs[0][ldK + 0][ldRow] = bF.x; Bs[0][ldK + 1][ldRow] = bF.y;
    Bs[0][ldK + 2][ldRow] = bF.z; Bs[0][ldK + 3][ldRow] = bF.w;
    __syncthreads();

    int nk = K >> 3;
    for (int kt = 0; kt < nk; kt++) {
        int cur = kt & 1;
        bool hasNext = (kt + 1 < nk);
        if (hasNext) {
            aF = *(const float4*)(Aptr + (kt + 1) * 8);
            bF = *(const float4*)(Bptr + (kt + 1) * 8);
        }
        #pragma unroll
        for (int k = 0; k < 8; k++) {
            float4 a0 = *(const float4*)&As[cur][k][rowBase];
            float4 a1 = *(const float4*)&As[cur][k][rowBase + 4];
            float4 b0 = *(const float4*)&Bs[cur][k][colBase];
            float4 b1 = *(const float4*)&Bs[cur][k][colBase + 4];
            float av[8] = {a0.x, a0.y, a0.z, a0.w, a1.x, a1.y, a1.z, a1.w};
            float bv[8] = {b0.x, b0.y, b0.z, b0.w, b1.x, b1.y, b1.z, b1.w};
            #pragma unroll
            for (int i = 0; i < 8; i++)
                #pragma unroll
                for (int j = 0; j < 8; j++)
                    acc[i][j] += av[i] * bv[j];
        }
        if (hasNext) {
            int nx = cur ^ 1;
            As[nx][ldK + 0][ldRow] = aF.x; As[nx][ldK + 1][ldRow] = aF.y;
            As[nx][ldK + 2][ldRow] = aF.z; As[nx][ldK + 3][ldRow] = aF.w;
            Bs[nx][ldK + 0][ldRow] = bF.x; Bs[nx][ldK + 1][ldRow] = bF.y;
            Bs[nx][ldK + 2][ldRow] = bF.z; Bs[nx][ldK + 3][ldRow] = bF.w;
        }
        __syncthreads();
    }

    // epilogue: vectorized float4 stores
    #pragma unroll
    for (int i = 0; i < 8; i++) {
        int m = m0 + rowBase + i;
        #pragma unroll
        for (int jq = 0; jq < 2; jq++) {
            int n = n0 + colBase + jq * 4;
            float4 v;
            v.x = acc[i][jq * 4 + 0] * alpha;
            v.y = acc[i][jq * 4 + 1] * alpha;
            v.z = acc[i][jq * 4 + 2] * alpha;
            v.w = acc[i][jq * 4 + 3] * alpha;
            if (bias) {
                float4 bb = *(const float4*)(bias + n);
                v.x += bb.x; v.y += bb.y; v.z += bb.z; v.w += bb.w;
            }
            if (doRelu) {
                v.x = fmaxf(v.x, 0.f); v.y = fmaxf(v.y, 0.f);
                v.z = fmaxf(v.z, 0.f); v.w = fmaxf(v.w, 0.f);
            }
            size_t ci = (size_t)m * ldc + n;
            if (res) {
                float4 rr = *(const float4*)(res + ci);
                v.x += rr.x; v.y += rr.y; v.z += rr.z; v.w += rr.w;
            }
            *(float4*)(Cp + ci) = v;
        }
    }
}

// ---------------------------------------------------------------------------
// Temporal causal attention. One block per (b,h). K,V fully resident in smem.
// 8 warps; warp w processes query tiles w and 15-w. Lane owns one query row;
// register-resident online softmax. q pre-scaled by 1/sqrt(32).
// ---------------------------------------------------------------------------
__global__ __launch_bounds__(256) void attn_t_kernel(
    const float* __restrict__ q, const float* __restrict__ k,
    const float* __restrict__ v, float* __restrict__ o)
{
    extern __shared__ float smem[];
    float4* Ks = (float4*)smem;             // [Tn][8] float4
    float4* Vs = (float4*)(smem + Tn * 32); // [Tn][8] float4

    int bh = blockIdx.x;
    int b = bh / Hn, h = bh % Hn;
    const size_t base = (size_t)b * Tn * Cn + (size_t)h * 32;

    for (int i = threadIdx.x; i < Tn * 8; i += 256) {
        int s = i >> 3, d4 = i & 7;
        Ks[i] = *(const float4*)(k + base + (size_t)s * Cn + d4 * 4);
        Vs[i] = *(const float4*)(v + base + (size_t)s * Cn + d4 * 4);
    }
    __syncthreads();

    int warp = threadIdx.x >> 5;
    int lane = threadIdx.x & 31;

    for (int pass = 0; pass < 2; pass++) {
        int qt = (pass == 0) ? warp : (15 - warp);
        int t = qt * 32 + lane;

        float qr[32];
        #pragma unroll
        for (int d4 = 0; d4 < 8; d4++) {
            float4 qv = *(const float4*)(q + base + (size_t)t * Cn + d4 * 4);
            qr[d4 * 4 + 0] = qv.x; qr[d4 * 4 + 1] = qv.y;
            qr[d4 * 4 + 2] = qv.z; qr[d4 * 4 + 3] = qv.w;
        }

        float m = -INFINITY, l = 0.f;
        float oa[32];
        #pragma unroll
        for (int d = 0; d < 32; d++) oa[d] = 0.f;

        for (int st = 0; st <= qt; st++) {
            float sc[32];
            float mx = -INFINITY;
            #pragma unroll
            for (int sk = 0; sk < 32; sk++) {
                int s = st * 32 + sk;
                float a = 0.f;
                #pragma unroll
                for (int d4 = 0; d4 < 8; d4++) {
                    float4 kk = Ks[s * 8 + d4];
                    a += qr[d4 * 4 + 0] * kk.x + qr[d4 * 4 + 1] * kk.y
                       + qr[d4 * 4 + 2] * kk.z + qr[d4 * 4 + 3] * kk.w;
                }
                if (st == qt && sk > lane) a = -INFINITY;
                sc[sk] = a;
                mx = fmaxf(mx, a);
            }
            float mn = fmaxf(m, mx);
            float f = expf(m - mn);
            l *= f;
            #pragma unroll
            for (int d = 0; d < 32; d++) oa[d] *= f;

            #pragma unroll
            for (int sk = 0; sk < 32; sk++) {
                float p = expf(sc[sk] - mn);
                l += p;
                int s = st * 32 + sk;
                #pragma unroll
                for (int d4 = 0; d4 < 8; d4++) {
                    float4 vv = Vs[s * 8 + d4];
                    oa[d4 * 4 + 0] += p * vv.x; oa[d4 * 4 + 1] += p * vv.y;
                    oa[d4 * 4 + 2] += p * vv.z; oa[d4 * 4 + 3] += p * vv.w;
                }
            }
            m = mn;
        }

        float inv = 1.f / l;
        #pragma unroll
        for (int d4 = 0; d4 < 8; d4++) {
            float4 w4;
            w4.x = oa[d4 * 4 + 0] * inv; w4.y = oa[d4 * 4 + 1] * inv;
            w4.z = oa[d4 * 4 + 2] * inv; w4.w = oa[d4 * 4 + 3] * inv;
            *(float4*)(o + base + (size_t)t * Cn + d4 * 4) = w4;
        }
    }
}

// ---------------------------------------------------------------------------
// Spatial: per (b,c) row, softmax over e for each head, mean over heads.
// ---------------------------------------------------------------------------
__global__ __launch_bounds__(256) void softmax_mean_kernel(
    const float* __restrict__ sc, float* __restrict__ sw)
{
    int bc = blockIdx.x;
    int b = bc / Cn, c = bc % Cn;
    int e = threadIdx.x;
    __shared__ float red[256];

    float acc = 0.f;
    for (int h = 0; h < Hn; h++) {
        float s = sc[(((size_t)(b * Hn + h) * Cn) + c) * Cn + e];
        red[e] = s; __syncthreads();
        for (int off = 128; off > 0; off >>= 1) {
            if (e < off) red[e] = fmaxf(red[e], red[e + off]);
            __syncthreads();
        }
        float mx = red[0]; __syncthreads();
        float p = expf(s - mx);
        red[e] = p; __syncthreads();
        for (int off = 128; off > 0; off >>= 1) {
            if (e < off) red[e] += red[e + off];
            __syncthreads();
        }
        acc += p / red[0];
        __syncthreads();
    }
    sw[(size_t)bc * Cn + e] = acc * (1.f / Hn);
}

// ---------------------------------------------------------------------------
// Host side
// ---------------------------------------------------------------------------
static void launch_gemm(const float* A, int lda, const float* Bp, int ldb,
                        float* Cp, int ldc, const float* bias, const float* res,
                        int M, int N, int K, float alpha, int doRelu,
                        int nz = 1,
                        long long zAo = 0, long long zAi = 0,
                        long long zBo = 0, long long zBi = 0,
                        long long zC = 0, long long zR = 0, int hd = 1)
{
    dim3 g(N / 128, M / 128, nz), blk(256);
    gemm_nt<<<g, blk>>>(A, lda, Bp, ldb, Cp, ldc, bias, res, K, alpha, doRelu,
                        zAo, zAi, zBo, zBi, zC, zR, hd);
}

extern "C" void kernel_launch(void* const* d_in, const int* in_sizes, int n_in,
                              void* d_out, int out_size)
{
    const float* x_T     = (const float*)d_in[0];
    const float* x_S     = (const float*)d_in[1];
    const float* Wq_t    = (const float*)d_in[2];
    const float* Wk_t    = (const float*)d_in[3];
    const float* Wv_t    = (const float*)d_in[4];
    const float* Wo      = (const float*)d_in[5];
    const float* Wq_s    = (const float*)d_in[6];
    const float* Wk_s    = (const float*)d_in[7];
    const float* ff1_w1  = (const float*)d_in[8];
    const float* ff1_b1  = (const float*)d_in[9];
    const float* ff1_w2  = (const float*)d_in[10];
    const float* ff1_b2  = (const float*)d_in[11];
    const float* ff2_w1  = (const float*)d_in[12];
    const float* ff2_b1  = (const float*)d_in[13];
    const float* ff2_w2  = (const float*)d_in[14];
    const float* ff2_b2  = (const float*)d_in[15];
    const float* t_ln1_w = (const float*)d_in[16];
    const float* t_ln1_b = (const float*)d_in[17];
    const float* t_ln2_w = (const float*)d_in[18];
    const float* t_ln2_b = (const float*)d_in[19];
    const float* s_ln1_w = (const float*)d_in[20];
    const float* s_ln1_b = (const float*)d_in[21];
    const float* fus_ln_w = (const float*)d_in[22];
    const float* fus_ln_b = (const float*)d_in[23];

    float* S = nullptr;
    cudaGetSymbolAddress((void**)&S, g_scratch);

    float* out = (float*)d_out;            // [B,T,C]
    float* sw  = out + SZ_BTC;             // [B,C,C] spatial_weights

    cudaFuncSetAttribute(attn_t_kernel,
                         cudaFuncAttributeMaxDynamicSharedMemorySize, 131072);

    const float iq = 0.17677669529663687f;  // 1/sqrt(32)

    // ---- temporal branch ----
    ln_kernel<<<Bn * Tn, 256>>>(x_T, t_ln1_w, t_ln1_b, S + OFF_H, Cn);
    launch_gemm(S + OFF_H, Cn, Wq_t, Cn, S + OFF_Q, Cn, nullptr, nullptr,
                Bn * Tn, Cn, Cn, iq, 0);
    launch_gemm(S + OFF_H, Cn, Wk_t, Cn, S + OFF_K, Cn, nullptr, nullptr,
                Bn * Tn, Cn, Cn, 1.f, 0);
    launch_gemm(S + OFF_H, Cn, Wv_t, Cn, S + OFF_V, Cn, nullptr, nullptr,
                Bn * Tn, Cn, Cn, 1.f, 0);
    attn_t_kernel<<<Bn * Hn, 256, 131072>>>(S + OFF_Q, S + OFF_K, S + OFF_V,
                                            S + OFF_O);
    launch_gemm(S + OFF_O, Cn, Wo, Cn, S + OFF_X, Cn, nullptr, x_T,
                Bn * Tn, Cn, Cn, 1.f, 0);
    ln_kernel<<<Bn * Tn, 256>>>(S + OFF_X, t_ln2_w, t_ln2_b, S + OFF_H, Cn);
    launch_gemm(S + OFF_H, Cn, ff1_w1, Cn, S + OFF_FFH, FFn, ff1_b1, nullptr,
                Bn * Tn, FFn, Cn, 1.f, 1);
    launch_gemm(S + OFF_FFH, FFn, ff1_w2, FFn, S + OFF_TOUT, Cn, ff1_b2,
                S + OFF_X, Bn * Tn, Cn, FFn, 1.f, 0);

    // ---- spatial branch ----
    ln_kernel<<<Bn * Cn, 256>>>(x_S, s_ln1_w, s_ln1_b, S + OFF_HS, Tn);
    launch_gemm(S + OFF_HS, Tn, Wq_s, Tn, S + OFF_QS, Hn * 64, nullptr, nullptr,
                Bn * Cn, Hn * 64, Tn, 1.f, 0);
    launch_gemm(S + OFF_HS, Tn, Wk_s, Tn, S + OFF_KS, Hn * 64, nullptr, nullptr,
                Bn * Cn, Hn * 64, Tn, 1.f, 0);
    // sc[b,h] = 0.125 * qs_bh @ ks_bh^T   (batched over z = b*H + h)
    launch_gemm(S + OFF_QS, Hn * 64, S + OFF_KS, Hn * 64, S + OFF_SC, Cn,
                nullptr, nullptr, Cn, Cn, 64, 0.125f, 0,
                Bn * Hn,
                (long long)Cn * (Hn * 64), 64,
                (long long)Cn * (Hn * 64), 64,
                (long long)Cn * Cn, 0, Hn);
    softmax_mean_kernel<<<Bn * Cn, 256>>>(S + OFF_SC, sw);

    // ---- fusion: x2 = tout + tout @ sw^T  (batched over b) ----
    launch_gemm(S + OFF_TOUT, Cn, sw, Cn, S + OFF_X2, Cn, nullptr,
                S + OFF_TOUT, Tn, Cn, Cn, 1.f, 0,
                Bn,
                (long long)Tn * Cn, 0,
                (long long)Cn * Cn, 0,
                (long long)Tn * Cn, (long long)Tn * Cn, 1);

    // ---- FFN2 -> out ----
    ln_kernel<<<Bn * Tn, 256>>>(S + OFF_X2, fus_ln_w, fus_ln_b, S + OFF_H, Cn);
    launch_gemm(S + OFF_H, Cn, ff2_w1, Cn, S + OFF_FFH, FFn, ff2_b1, nullptr,
                Bn * Tn, FFn, Cn, 1.f, 1);
    launch_gemm(S + OFF_FFH, FFn, ff2_w2, FFn, out, Cn, ff2_b2, S + OFF_X2,
                Bn * Tn, Cn, FFn, 1.f, 0);
}

// round 9
// speedup vs baseline: 1.7479x; 1.4477x over previous
#include <cuda_runtime.h>
#include <cuda_bf16.h>
#include <stdint.h>
#include <math.h>

#define Bn 16
#define Tn 512
#define Cn 256
#define Hn 8
#define FFn 1024
#define LNEPS 1e-6f

#define SZ_BTC (Bn*Tn*Cn)     /* 2,097,152 */

// ---------------- fp32 scratch ----------------
#define OFF_Q    0
#define OFF_K    (SZ_BTC*1)
#define OFF_V    (SZ_BTC*2)
#define OFF_X    (SZ_BTC*3)
#define OFF_TOUT (SZ_BTC*4)
#define OFF_X2   (SZ_BTC*5)
#define OFF_SC   (SZ_BTC*6)                     /* B*H*C*C = 8,388,608 */
#define TOTAL_F32 (SZ_BTC*6 + Bn*Hn*Cn*Cn)

__device__ float g_f32[TOTAL_F32];

// ---------------- bf16 split scratch (layout [R][2K]: hi block | lo block) --
#define BH1   0                                 /* 8192 x 512  */
#define BH2   (BH1 + 8192*512)
#define BH3   (BH2 + 8192*512)
#define BHS   (BH3 + 8192*512)                  /* 4096 x 1024 */
#define BO    (BHS + 4096*1024)                 /* 8192 x 512  */
#define BFFH  (BO  + 8192*512)                  /* 8192 x 2048 */
#define BQS   (BFFH + 8192*2048)                /* 4096 x 1024 */
#define BKS   (BQS + 4096*1024)
#define BTOUT (BKS + 4096*1024)                 /* 8192 x 512  */
#define BSW   (BTOUT + 8192*512)                /* 4096 x 512  */
#define BWQT  (BSW + 4096*512)                  /* 256 x 512   */
#define BWKT  (BWQT + 256*512)
#define BWVT  (BWKT + 256*512)
#define BWO   (BWVT + 256*512)
#define BWQS  (BWO  + 256*512)                  /* 512 x 1024  */
#define BWKS  (BWQS + 512*1024)
#define BW11  (BWKS + 512*1024)                 /* 1024 x 512  */
#define BW12  (BW11 + 1024*512)                 /* 256 x 2048  */
#define BW21  (BW12 + 256*2048)
#define BW22  (BW21 + 1024*512)
#define TOTAL_BF (BW22 + 256*2048)

__device__ __nv_bfloat16 g_bf[TOTAL_BF];

// ===========================================================================
// helpers (portable: mma.sync + ldmatrix + cp.async, NO 'a'-suffix features)
// ===========================================================================
__device__ __forceinline__ uint32_t smem_u32(const void* p) {
    uint32_t a;
    asm("{ .reg .u64 t; cvta.to.shared.u64 t, %1; cvt.u32.u64 %0, t; }"
        : "=r"(a) : "l"(p));
    return a;
}
__device__ __forceinline__ void cp16(uint32_t dst, const void* src) {
    asm volatile("cp.async.cg.shared.global [%0], [%1], 16;"
                 :: "r"(dst), "l"(__cvta_generic_to_global(src)) : "memory");
}
#define CP_COMMIT() asm volatile("cp.async.commit_group;" ::: "memory")
#define CP_WAIT(n)  asm volatile("cp.async.wait_group %0;" :: "n"(n) : "memory")

__device__ __forceinline__ void ldsm4(uint32_t* r, uint32_t a) {
    asm volatile("ldmatrix.sync.aligned.m8n8.x4.shared.b16 {%0,%1,%2,%3}, [%4];"
                 : "=r"(r[0]), "=r"(r[1]), "=r"(r[2]), "=r"(r[3]) : "r"(a));
}
__device__ __forceinline__ void ldsm2(uint32_t* r, uint32_t a) {
    asm volatile("ldmatrix.sync.aligned.m8n8.x2.shared.b16 {%0,%1}, [%2];"
                 : "=r"(r[0]), "=r"(r[1]) : "r"(a));
}
__device__ __forceinline__ void mma16816(float* c, const uint32_t* a,
                                         const uint32_t* b) {
    asm volatile(
        "mma.sync.aligned.m16n8k16.row.col.f32.bf16.bf16.f32 "
        "{%0,%1,%2,%3}, {%4,%5,%6,%7}, {%8,%9}, {%0,%1,%2,%3};"
        : "+f"(c[0]), "+f"(c[1]), "+f"(c[2]), "+f"(c[3])
        : "r"(a[0]), "r"(a[1]), "r"(a[2]), "r"(a[3]), "r"(b[0]), "r"(b[1]));
}

__device__ __forceinline__ unsigned pk2(float a, float b) {
    return ((unsigned)__bfloat16_as_ushort(__float2bfloat16(b)) << 16)
         | (unsigned)__bfloat16_as_ushort(__float2bfloat16(a));
}
__device__ __forceinline__ float rezf(float a) {
    return a - __bfloat162float(__float2bfloat16(a));
}

// ===========================================================================
// cvt: fp32 [R x K] -> bf16 split [R x 2K]
// ===========================================================================
__global__ __launch_bounds__(256) void cvt_split(
    const float* __restrict__ in, __nv_bfloat16* __restrict__ out, int n, int K)
{
    int i = blockIdx.x * 256 + threadIdx.x;
    if (i >= n) return;
    int r = i / K, c = i - r * K;
    float f = in[i];
    __nv_bfloat16 h = __float2bfloat16(f);
    out[(size_t)r * 2 * K + c] = h;
    out[(size_t)r * 2 * K + K + c] = __float2bfloat16(f - __bfloat162float(h));
}

// ===========================================================================
// LayerNorm -> split bf16 out [row][2N]
// ===========================================================================
__global__ __launch_bounds__(256) void ln_split(
    const float* __restrict__ x, const float* __restrict__ w,
    const float* __restrict__ b, __nv_bfloat16* __restrict__ outS, int N)
{
    int row = blockIdx.x;
    const float* xr = x + (size_t)row * N;
    __nv_bfloat16* orow = outS + (size_t)row * 2 * N;
    __shared__ float red[256];
    int tid = threadIdx.x;

    float s = 0.f;
    for (int i = tid; i < N; i += 256) s += xr[i];
    red[tid] = s; __syncthreads();
    for (int off = 128; off > 0; off >>= 1) {
        if (tid < off) red[tid] += red[tid + off];
        __syncthreads();
    }
    float mean = red[0] / N;
    __syncthreads();
    float v = 0.f;
    for (int i = tid; i < N; i += 256) { float d = xr[i] - mean; v += d * d; }
    red[tid] = v; __syncthreads();
    for (int off = 128; off > 0; off >>= 1) {
        if (tid < off) red[tid] += red[tid + off];
        __syncthreads();
    }
    float rstd = rsqrtf(red[0] / N + LNEPS);

    for (int i = tid; i < N; i += 256) {
        float val = (xr[i] - mean) * rstd * w[i] + b[i];
        __nv_bfloat16 h = __float2bfloat16(val);
        orow[i] = h;
        orow[N + i] = __float2bfloat16(val - __bfloat162float(h));
    }
}

// ===========================================================================
// Tensor-core GEMM (mma.sync bf16, split-precision 3 terms):
//   C[m,n] = alpha * sum_k A[m,k]*B[n,k]  (+bias)(relu)(+res)
// A,B split-bf16 [rows][2*Ktot]. Tile 128x128, BK=32, 8 warps of 64x32.
// cp.async double-buffered. outMode: 0=fp32, 1=split bf16, 2=both.
// ===========================================================================
#define PADK 40   /* bf16 per smem row (32 data + 8 pad); 80B rows */

__global__ __launch_bounds__(256, 2) void gemm_mma(
    const __nv_bfloat16* __restrict__ A, int ldA, int KtotA,
    const __nv_bfloat16* __restrict__ Bp, int ldB, int KtotB,
    int Kterm,
    float* __restrict__ Cp, int ldc,
    __nv_bfloat16* __restrict__ Os, int ldOs, int KtotO,
    const float* __restrict__ bias, const float* __restrict__ res,
    float alpha, int doRelu, int outMode,
    long long zAo, long long zAi, long long zBo, long long zBi,
    long long zC, long long zR, int hd)
{
    __shared__ __align__(16) __nv_bfloat16 sA[2][128][PADK];
    __shared__ __align__(16) __nv_bfloat16 sB[2][128][PADK];

    int tid = threadIdx.x;
    int wid = tid >> 5, lane = tid & 31;

    int z = blockIdx.z;
    A  += (long long)(z / hd) * zAo + (long long)(z % hd) * zAi;
    Bp += (long long)(z / hd) * zBo + (long long)(z % hd) * zBi;
    int m0 = blockIdx.y * 128, n0 = blockIdx.x * 128;

    // warp tile: 2 rows x 4 cols of 64x32
    int wm0 = (wid >> 2) * 64;
    int wn0 = (wid & 3) * 32;

    // cp.async mapping: thread covers 2 chunks per matrix; chunk = 16B = 8 bf16
    int ldRow0 = tid >> 2;            // 0..63
    int ldChunk = (tid & 3) * 8;      // bf16 col 0,8,16,24
    uint32_t sA0 = smem_u32(&sA[0][0][0]);
    uint32_t sB0 = smem_u32(&sB[0][0][0]);
    const uint32_t bufStride = 128 * PADK * 2;   // bytes per buffer

    // ldmatrix lane geometry
    int q = lane >> 3, i8 = lane & 7;
    int aLaneRow = i8 + (q & 1) * 8;              // row within m16 tile
    int aLaneCol = (q >> 1) * 8;                  // 0 or 8 within k16
    int bLaneRow = i8;                            // row within n8 tile
    int bLaneCol = ((lane >> 3) & 1) * 8;         // 0 or 8 (lanes 0..15 matter)

    const int aT[3] = {0, 0, 1}, bT[3] = {0, 1, 0};
    int kc = Kterm >> 5;        // 32-wide chunks per term
    int nc = 3 * kc;

    float acc[4][4][4] = {};

    // ---- issue chunk 0 loads ----
    {
        int aCol0 = 0 * KtotA + 0 + ldChunk;   // term 0, w 0
        #pragma unroll
        for (int u = 0; u < 2; u++) {
            int rr = ldRow0 + u * 64;
            cp16(sA0 + (rr * PADK + ldChunk) * 2,
                 A + (size_t)(m0 + rr) * ldA + aCol0);
            cp16(sB0 + (rr * PADK + ldChunk) * 2,
                 Bp + (size_t)(n0 + rr) * ldB + aCol0 - ldChunk + ldChunk); // same col for B term0
        }
        CP_COMMIT();
    }

    for (int ci = 0; ci < nc; ci++) {
        int cur = ci & 1;
        if (ci + 1 < nc) {
            int nxt = cur ^ 1;
            int term = (ci + 1) / kc, w = (ci + 1) % kc;
            int aCol = aT[term] * KtotA + w * 32 + ldChunk;
            int bCol = bT[term] * KtotB + w * 32 + ldChunk;
            #pragma unroll
            for (int u = 0; u < 2; u++) {
                int rr = ldRow0 + u * 64;
                cp16(sA0 + nxt * bufStride + (rr * PADK + ldChunk) * 2,
                     A + (size_t)(m0 + rr) * ldA + aCol);
                cp16(sB0 + nxt * bufStride + (rr * PADK + ldChunk) * 2,
                     Bp + (size_t)(n0 + rr) * ldB + bCol);
            }
            CP_COMMIT();
            CP_WAIT(1);
        } else {
            CP_WAIT(0);
        }
        __syncthreads();

        uint32_t aBase = sA0 + cur * bufStride;
        uint32_t bBase = sB0 + cur * bufStride;
        #pragma unroll
        for (int ks = 0; ks < 2; ks++) {
            int k0 = ks * 16;
            uint32_t af[4][4], bf2[4][2];
            #pragma unroll
            for (int mi = 0; mi < 4; mi++)
                ldsm4(af[mi], aBase +
                      ((wm0 + mi * 16 + aLaneRow) * PADK + k0 + aLaneCol) * 2);
            #pragma unroll
            for (int ni = 0; ni < 4; ni++)
                ldsm2(bf2[ni], bBase +
                      ((wn0 + ni * 8 + bLaneRow) * PADK + k0 + bLaneCol) * 2);
            #pragma unroll
            for (int mi = 0; mi < 4; mi++)
                #pragma unroll
                for (int ni = 0; ni < 4; ni++)
                    mma16816(acc[mi][ni], af[mi], bf2[ni]);
        }
        __syncthreads();
    }

    // ---- epilogue ----
    int lr = lane >> 2;           // 0..7
    int lc = (lane & 3) * 2;      // 0,2,4,6
    #pragma unroll
    for (int mi = 0; mi < 4; mi++) {
        #pragma unroll
        for (int s = 0; s < 2; s++) {
            int m = m0 + wm0 + mi * 16 + lr + s * 8;
            #pragma unroll
            for (int ni = 0; ni < 4; ni++) {
                int n = n0 + wn0 + ni * 8 + lc;
                float v0 = acc[mi][ni][2 * s + 0] * alpha;
                float v1 = acc[mi][ni][2 * s + 1] * alpha;
                if (bias) { v0 += bias[n]; v1 += bias[n + 1]; }
                if (doRelu) { v0 = fmaxf(v0, 0.f); v1 = fmaxf(v1, 0.f); }
                if (res) {
                    const float2 r2 = *(const float2*)(res + (long long)z * zR
                                       + (size_t)m * ldc + n);
                    v0 += r2.x; v1 += r2.y;
                }
                if (outMode != 1) {
                    float2 o2 = make_float2(v0, v1);
                    *(float2*)(Cp + (long long)z * zC + (size_t)m * ldc + n) = o2;
                }
                if (outMode >= 1) {
                    __nv_bfloat16* op = Os + (size_t)m * ldOs + n;
                    *(uint32_t*)op = pk2(v0, v1);
                    *(uint32_t*)(op + KtotO) = pk2(rezf(v0), rezf(v1));
                }
            }
        }
    }
}

// ===========================================================================
// Temporal causal attention (fp32 in, split-bf16 out). Block per (b,h).
// ===========================================================================
__global__ __launch_bounds__(256) void attn_t_kernel(
    const float* __restrict__ q, const float* __restrict__ k,
    const float* __restrict__ v, __nv_bfloat16* __restrict__ op)
{
    extern __shared__ float smem[];
    float4* Ks = (float4*)smem;
    float4* Vs = (float4*)(smem + Tn * 32);

    int bh = blockIdx.x;
    int b = bh / Hn, h = bh % Hn;
    const size_t base = (size_t)b * Tn * Cn + (size_t)h * 32;

    for (int i = threadIdx.x; i < Tn * 8; i += 256) {
        int s = i >> 3, d4 = i & 7;
        Ks[i] = *(const float4*)(k + base + (size_t)s * Cn + d4 * 4);
        Vs[i] = *(const float4*)(v + base + (size_t)s * Cn + d4 * 4);
    }
    __syncthreads();

    int warp = threadIdx.x >> 5;
    int lane = threadIdx.x & 31;

    for (int pass = 0; pass < 2; pass++) {
        int qt = (pass == 0) ? warp : (15 - warp);
        int t = qt * 32 + lane;

        float qr[32];
        #pragma unroll
        for (int d4 = 0; d4 < 8; d4++) {
            float4 qv = *(const float4*)(q + base + (size_t)t * Cn + d4 * 4);
            qr[d4*4+0] = qv.x; qr[d4*4+1] = qv.y; qr[d4*4+2] = qv.z; qr[d4*4+3] = qv.w;
        }

        float m = -INFINITY, l = 0.f;
        float oa[32];
        #pragma unroll
        for (int d = 0; d < 32; d++) oa[d] = 0.f;

        for (int st = 0; st <= qt; st++) {
            float scr[32];
            float mx = -INFINITY;
            #pragma unroll
            for (int sk = 0; sk < 32; sk++) {
                int s = st * 32 + sk;
                float a = 0.f;
                #pragma unroll
                for (int d4 = 0; d4 < 8; d4++) {
                    float4 kk = Ks[s * 8 + d4];
                    a += qr[d4*4+0]*kk.x + qr[d4*4+1]*kk.y
                       + qr[d4*4+2]*kk.z + qr[d4*4+3]*kk.w;
                }
                if (st == qt && sk > lane) a = -INFINITY;
                scr[sk] = a;
                mx = fmaxf(mx, a);
            }
            float mn = fmaxf(m, mx);
            float f = expf(m - mn);
            l *= f;
            #pragma unroll
            for (int d = 0; d < 32; d++) oa[d] *= f;

            #pragma unroll
            for (int sk = 0; sk < 32; sk++) {
                float p = expf(scr[sk] - mn);
                l += p;
                int s = st * 32 + sk;
                #pragma unroll
                for (int d4 = 0; d4 < 8; d4++) {
                    float4 vv = Vs[s * 8 + d4];
                    oa[d4*4+0] += p*vv.x; oa[d4*4+1] += p*vv.y;
                    oa[d4*4+2] += p*vv.z; oa[d4*4+3] += p*vv.w;
                }
            }
            m = mn;
        }

        float inv = 1.f / l;
        size_t rowp = ((size_t)b * Tn + t) * 512 + h * 32;
        #pragma unroll
        for (int g = 0; g < 4; g++) {
            float w0 = oa[g*8+0]*inv, w1 = oa[g*8+1]*inv, w2 = oa[g*8+2]*inv,
                  w3 = oa[g*8+3]*inv, w4 = oa[g*8+4]*inv, w5 = oa[g*8+5]*inv,
                  w6 = oa[g*8+6]*inv, w7 = oa[g*8+7]*inv;
            uint4 h4, l4;
            h4.x = pk2(w0, w1); h4.y = pk2(w2, w3);
            h4.z = pk2(w4, w5); h4.w = pk2(w6, w7);
            l4.x = pk2(rezf(w0), rezf(w1)); l4.y = pk2(rezf(w2), rezf(w3));
            l4.z = pk2(rezf(w4), rezf(w5)); l4.w = pk2(rezf(w6), rezf(w7));
            *(uint4*)(op + rowp + g * 8) = h4;
            *(uint4*)(op + rowp + 256 + g * 8) = l4;
        }
    }
}

// ===========================================================================
// Spatial softmax + head-mean: sc [B,H,C,C] -> sw fp32 [B,C,C] + split bf16
// ===========================================================================
__global__ __launch_bounds__(256) void softmax_mean_kernel(
    const float* __restrict__ scp, float* __restrict__ sw,
    __nv_bfloat16* __restrict__ swp)
{
    int bc = blockIdx.x;
    int b = bc / Cn, c = bc % Cn;
    int e = threadIdx.x;
    __shared__ float red[256];

    float acc = 0.f;
    for (int h = 0; h < Hn; h++) {
        float s = scp[(((size_t)(b * Hn + h) * Cn) + c) * Cn + e];
        red[e] = s; __syncthreads();
        for (int off = 128; off > 0; off >>= 1) {
            if (e < off) red[e] = fmaxf(red[e], red[e + off]);
            __syncthreads();
        }
        float mx = red[0]; __syncthreads();
        float p = expf(s - mx);
        red[e] = p; __syncthreads();
        for (int off = 128; off > 0; off >>= 1) {
            if (e < off) red[e] += red[e + off];
            __syncthreads();
        }
        acc += p / red[0];
        __syncthreads();
    }
    float val = acc * (1.f / Hn);
    sw[(size_t)bc * Cn + e] = val;
    __nv_bfloat16 h16 = __float2bfloat16(val);
    swp[(size_t)bc * 512 + e] = h16;
    swp[(size_t)bc * 512 + 256 + e] = __float2bfloat16(val - __bfloat162float(h16));
}

// ===========================================================================
// Host side
// ===========================================================================
typedef long long ll;
typedef __nv_bfloat16 bf;

static void g_tc(const bf* A, int ldA, int KA, const bf* B, int ldB, int KB,
                 int Kterm, float* C, int ldc, bf* Os, int ldOs, int KO,
                 const float* bias, const float* res, float alpha, int relu,
                 int mode, int M, int N, int nz = 1,
                 ll zAo = 0, ll zAi = 0, ll zBo = 0, ll zBi = 0,
                 ll zC = 0, ll zR = 0, int hd = 1)
{
    dim3 g(N / 128, M / 128, nz);
    gemm_mma<<<g, 256>>>(A, ldA, KA, B, ldB, KB, Kterm, C, ldc,
                         Os, ldOs, KO, bias, res, alpha, relu, mode,
                         zAo, zAi, zBo, zBi, zC, zR, hd);
}

extern "C" void kernel_launch(void* const* d_in, const int* in_sizes, int n_in,
                              void* d_out, int out_size)
{
    const float* x_T     = (const float*)d_in[0];
    const float* x_S     = (const float*)d_in[1];
    const float* Wq_t    = (const float*)d_in[2];
    const float* Wk_t    = (const float*)d_in[3];
    const float* Wv_t    = (const float*)d_in[4];
    const float* Wo      = (const float*)d_in[5];
    const float* Wq_s    = (const float*)d_in[6];
    const float* Wk_s    = (const float*)d_in[7];
    const float* ff1_w1  = (const float*)d_in[8];
    const float* ff1_b1  = (const float*)d_in[9];
    const float* ff1_w2  = (const float*)d_in[10];
    const float* ff1_b2  = (const float*)d_in[11];
    const float* ff2_w1  = (const float*)d_in[12];
    const float* ff2_b1  = (const float*)d_in[13];
    const float* ff2_w2  = (const float*)d_in[14];
    const float* ff2_b2  = (const float*)d_in[15];
    const float* t_ln1_w = (const float*)d_in[16];
    const float* t_ln1_b = (const float*)d_in[17];
    const float* t_ln2_w = (const float*)d_in[18];
    const float* t_ln2_b = (const float*)d_in[19];
    const float* s_ln1_w = (const float*)d_in[20];
    const float* s_ln1_b = (const float*)d_in[21];
    const float* fus_ln_w = (const float*)d_in[22];
    const float* fus_ln_b = (const float*)d_in[23];

    float* S = nullptr;
    cudaGetSymbolAddress((void**)&S, g_f32);
    bf* Bm = nullptr;
    cudaGetSymbolAddress((void**)&Bm, g_bf);

    float* out = (float*)d_out;
    float* sw  = out + SZ_BTC;

    cudaFuncSetAttribute(attn_t_kernel,
                         cudaFuncAttributeMaxDynamicSharedMemorySize, 131072);

    const float iq = 0.17677669529663687f;  // 1/sqrt(32)

    // ---- weight conversions ----
    struct { const float* in; int off, n, K; } wc[10] = {
        {Wq_t,  BWQT, 256*256, 256}, {Wk_t, BWKT, 256*256, 256},
        {Wv_t,  BWVT, 256*256, 256}, {Wo,   BWO,  256*256, 256},
        {Wq_s,  BWQS, 512*512, 512}, {Wk_s, BWKS, 512*512, 512},
        {ff1_w1, BW11, 1024*256, 256}, {ff1_w2, BW12, 256*1024, 1024},
        {ff2_w1, BW21, 1024*256, 256}, {ff2_w2, BW22, 256*1024, 1024},
    };
    for (int i = 0; i < 10; i++)
        cvt_split<<<(wc[i].n + 255) / 256, 256>>>(wc[i].in, Bm + wc[i].off,
                                                  wc[i].n, wc[i].K);

    // ---- temporal branch ----
    ln_split<<<Bn * Tn, 256>>>(x_T, t_ln1_w, t_ln1_b, Bm + BH1, Cn);
    g_tc(Bm + BH1, 512, 256, Bm + BWQT, 512, 256, 256,
         S + OFF_Q, Cn, nullptr, 0, 0, nullptr, nullptr, iq, 0, 0, 8192, 256);
    g_tc(Bm + BH1, 512, 256, Bm + BWKT, 512, 256, 256,
         S + OFF_K, Cn, nullptr, 0, 0, nullptr, nullptr, 1.f, 0, 0, 8192, 256);
    g_tc(Bm + BH1, 512, 256, Bm + BWVT, 512, 256, 256,
         S + OFF_V, Cn, nullptr, 0, 0, nullptr, nullptr, 1.f, 0, 0, 8192, 256);
    attn_t_kernel<<<Bn * Hn, 256, 131072>>>(S + OFF_Q, S + OFF_K, S + OFF_V,
                                            Bm + BO);
    g_tc(Bm + BO, 512, 256, Bm + BWO, 512, 256, 256,
         S + OFF_X, Cn, nullptr, 0, 0, nullptr, x_T, 1.f, 0, 0, 8192, 256);
    ln_split<<<Bn * Tn, 256>>>(S + OFF_X, t_ln2_w, t_ln2_b, Bm + BH2, Cn);
    g_tc(Bm + BH2, 512, 256, Bm + BW11, 512, 256, 256,
         nullptr, 0, Bm + BFFH, 2048, 1024, ff1_b1, nullptr, 1.f, 1, 1,
         8192, 1024);
    g_tc(Bm + BFFH, 2048, 1024, Bm + BW12, 2048, 1024, 1024,
         S + OFF_TOUT, Cn, Bm + BTOUT, 512, 256, ff1_b2, S + OFF_X,
         1.f, 0, 2, 8192, 256);

    // ---- spatial branch ----
    ln_split<<<Bn * Cn, 256>>>(x_S, s_ln1_w, s_ln1_b, Bm + BHS, Tn);
    g_tc(Bm + BHS, 1024, 512, Bm + BWQS, 1024, 512, 512,
         nullptr, 0, Bm + BQS, 1024, 512, nullptr, nullptr, 1.f, 0, 1,
         4096, 512);
    g_tc(Bm + BHS, 1024, 512, Bm + BWKS, 1024, 512, 512,
         nullptr, 0, Bm + BKS, 1024, 512, nullptr, nullptr, 1.f, 0, 1,
         4096, 512);
    // sc[b,h] = 0.125 * qs_bh @ ks_bh^T  (z = b*H + h)
    g_tc(Bm + BQS, 1024, 512, Bm + BKS, 1024, 512, 64,
         S + OFF_SC, Cn, nullptr, 0, 0, nullptr, nullptr, 0.125f, 0, 0,
         256, 256, Bn * Hn,
         (ll)256 * 1024, 64, (ll)256 * 1024, 64,
         (ll)Cn * Cn, 0, Hn);
    softmax_mean_kernel<<<Bn * Cn, 256>>>(S + OFF_SC, sw, Bm + BSW);

    // ---- fusion: x2 = tout + tout @ sw^T  (z = b) ----
    g_tc(Bm + BTOUT, 512, 256, Bm + BSW, 512, 256, 256,
         S + OFF_X2, Cn, nullptr, 0, 0, nullptr, S + OFF_TOUT, 1.f, 0, 0,
         512, 256, Bn,
         (ll)512 * 512, 0, (ll)256 * 512, 0,
         (ll)512 * 256, (ll)512 * 256, 1);

    // ---- FFN2 -> out ----
    ln_split<<<Bn * Tn, 256>>>(S + OFF_X2, fus_ln_w, fus_ln_b, Bm + BH3, Cn);
    g_tc(Bm + BH3, 512, 256, Bm + BW21, 512, 256, 256,
         nullptr, 0, Bm + BFFH, 2048, 1024, ff2_b1, nullptr, 1.f, 1, 1,
         8192, 1024);
    g_tc(Bm + BFFH, 2048, 1024, Bm + BW22, 2048, 1024, 1024,
         out, Cn, nullptr, 0, 0, ff2_b2, S + OFF_X2, 1.f, 0, 0, 8192, 256);
}

// round 16
// speedup vs baseline: 2.2075x; 1.2630x over previous
#include <cuda_runtime.h>
#include <cuda_bf16.h>
#include <stdint.h>
#include <math.h>

#define Bn 16
#define Tn 512
#define Cn 256
#define Hn 8
#define FFn 1024
#define LNEPS 1e-6f

#define SZ_BTC (Bn*Tn*Cn)     /* 2,097,152 */

// ---------------- fp32 scratch ----------------
#define OFF_QKV  0                              /* 8192 x 768 */
#define OFF_X    (SZ_BTC*3)
#define OFF_TOUT (SZ_BTC*4)
#define OFF_X2   (SZ_BTC*5)
#define OFF_SC   (SZ_BTC*6)                     /* B*H*C*C = 8,388,608 */
#define TOTAL_F32 (SZ_BTC*6 + Bn*Hn*Cn*Cn)

__device__ float g_f32[TOTAL_F32];

// ---------------- bf16 split scratch (layout [R][2K]: hi block | lo block) --
#define BH1   0                                 /* 8192 x 512  */
#define BH2   (BH1 + 8192*512)
#define BH3   (BH2 + 8192*512)
#define BHS   (BH3 + 8192*512)                  /* 4096 x 1024 */
#define BO    (BHS + 4096*1024)                 /* 8192 x 512  */
#define BFFH  (BO  + 8192*512)                  /* 8192 x 2048 */
#define BQKS  (BFFH + 8192*2048)                /* 4096 x 2048 */
#define BTOUT (BQKS + 4096*2048)                /* 8192 x 512  */
#define BSW   (BTOUT + 8192*512)                /* 4096 x 512  */
#define BWQKV (BSW + 4096*512)                  /* 768 x 512   */
#define BWO   (BWQKV + 768*512)                 /* 256 x 512   */
#define BWQKS (BWO + 256*512)                   /* 1024 x 1024 */
#define BW11  (BWQKS + 1024*1024)               /* 1024 x 512  */
#define BW12  (BW11 + 1024*512)                 /* 256 x 2048  */
#define BW21  (BW12 + 256*2048)
#define BW22  (BW21 + 1024*512)
#define TOTAL_BF (BW22 + 256*2048)

__device__ __nv_bfloat16 g_bf[TOTAL_BF];

typedef __nv_bfloat16 bf;

// ===========================================================================
// helpers (portable: mma.sync + ldmatrix + cp.async, NO 'a'-suffix features)
// ===========================================================================
__device__ __forceinline__ uint32_t smem_u32(const void* p) {
    uint32_t a;
    asm("{ .reg .u64 t; cvta.to.shared.u64 t, %1; cvt.u32.u64 %0, t; }"
        : "=r"(a) : "l"(p));
    return a;
}
__device__ __forceinline__ void cp16(uint32_t dst, const void* src) {
    asm volatile("cp.async.cg.shared.global [%0], [%1], 16;"
                 :: "r"(dst), "l"(__cvta_generic_to_global(src)) : "memory");
}
#define CP_COMMIT() asm volatile("cp.async.commit_group;" ::: "memory")
#define CP_WAIT1()  asm volatile("cp.async.wait_group 1;" ::: "memory")
#define CP_WAIT0()  asm volatile("cp.async.wait_group 0;" ::: "memory")

__device__ __forceinline__ void ldsm4(uint32_t* r, uint32_t a) {
    asm volatile("ldmatrix.sync.aligned.m8n8.x4.shared.b16 {%0,%1,%2,%3}, [%4];"
                 : "=r"(r[0]), "=r"(r[1]), "=r"(r[2]), "=r"(r[3]) : "r"(a));
}
__device__ __forceinline__ void ldsm2(uint32_t* r, uint32_t a) {
    asm volatile("ldmatrix.sync.aligned.m8n8.x2.shared.b16 {%0,%1}, [%2];"
                 : "=r"(r[0]), "=r"(r[1]) : "r"(a));
}
__device__ __forceinline__ void mma16816(float* c, const uint32_t* a,
                                         const uint32_t* b) {
    asm volatile(
        "mma.sync.aligned.m16n8k16.row.col.f32.bf16.bf16.f32 "
        "{%0,%1,%2,%3}, {%4,%5,%6,%7}, {%8,%9}, {%0,%1,%2,%3};"
        : "+f"(c[0]), "+f"(c[1]), "+f"(c[2]), "+f"(c[3])
        : "r"(a[0]), "r"(a[1]), "r"(a[2]), "r"(a[3]), "r"(b[0]), "r"(b[1]));
}

__device__ __forceinline__ unsigned pk2(float a, float b) {
    return ((unsigned)__bfloat16_as_ushort(__float2bfloat16(b)) << 16)
         | (unsigned)__bfloat16_as_ushort(__float2bfloat16(a));
}
__device__ __forceinline__ float rezf(float a) {
    return a - __bfloat162float(__float2bfloat16(a));
}

// ===========================================================================
// Fused weight conversion: 10 regions, fp32 [r][K] -> split bf16 [r][2K]*scale
// ===========================================================================
struct CvtArgs {
    const float* src[10];
    long long dst[10];
    int K[10];
    float scale[10];
    int bStart[11];
};

__global__ __launch_bounds__(256) void cvt_all(CvtArgs a, bf* __restrict__ out)
{
    int r = 0;
    #pragma unroll
    for (int j = 0; j < 9; j++) if ((int)blockIdx.x >= a.bStart[j + 1]) r = j + 1;
    int i = (blockIdx.x - a.bStart[r]) * 256 + threadIdx.x;
    int K = a.K[r];
    int row = i / K, c = i - row * K;
    float f = a.src[r][i] * a.scale[r];
    bf h = __float2bfloat16(f);
    long long base = a.dst[r] + (long long)row * 2 * K;
    out[base + c] = h;
    out[base + K + c] = __float2bfloat16(f - __bfloat162float(h));
}

// ===========================================================================
// LayerNorm, warp-per-row (no __syncthreads), split bf16 out [row][2N]
// ===========================================================================
template<int E>
__global__ __launch_bounds__(256) void ln_split_warp(
    const float* __restrict__ x, const float* __restrict__ wgt,
    const float* __restrict__ bias, bf* __restrict__ outS)
{
    const int N = E * 32;
    int row = blockIdx.x * 8 + (threadIdx.x >> 5);
    int lane = threadIdx.x & 31;
    const float* xr = x + (size_t)row * N;
    bf* orow = outS + (size_t)row * 2 * N;

    float v[E];
    float s = 0.f;
    #pragma unroll
    for (int i = 0; i < E; i++) { v[i] = xr[lane + 32 * i]; s += v[i]; }
    #pragma unroll
    for (int o = 16; o; o >>= 1) s += __shfl_xor_sync(~0u, s, o);
    float mean = s / N;
    float var = 0.f;
    #pragma unroll
    for (int i = 0; i < E; i++) { float d = v[i] - mean; var += d * d; }
    #pragma unroll
    for (int o = 16; o; o >>= 1) var += __shfl_xor_sync(~0u, var, o);
    float rstd = rsqrtf(var / N + LNEPS);

    #pragma unroll
    for (int i = 0; i < E; i++) {
        int idx = lane + 32 * i;
        float val = (v[i] - mean) * rstd * wgt[idx] + bias[idx];
        bf h = __float2bfloat16(val);
        orow[idx] = h;
        orow[N + idx] = __float2bfloat16(val - __bfloat162float(h));
    }
}

// ===========================================================================
// Tensor-core GEMM (mma.sync bf16, split-precision 3 terms):
//   C[m,n] = alpha * sum_k A[m,k]*B[n,k]  (+bias)(relu)(+res)
// A,B split-bf16 [rows][2*Ktot]. Tile 128x128, BK=32, 8 warps of 64x32.
// cp.async double-buffered (R9-proven core). outMode: 0=fp32,1=split,2=both.
// ===========================================================================
#define PADK 40   /* bf16 per smem row (32 data + 8 pad); 80B rows */

__global__ __launch_bounds__(256, 2) void gemm_mma(
    const bf* __restrict__ A, int ldA, int KtotA,
    const bf* __restrict__ Bp, int ldB, int KtotB,
    int Kterm,
    float* __restrict__ Cp, int ldc,
    bf* __restrict__ Os, int ldOs, int KtotO,
    const float* __restrict__ bias, const float* __restrict__ res,
    float alpha, int doRelu, int outMode,
    long long zAo, long long zAi, long long zBo, long long zBi,
    long long zC, long long zR, int hd)
{
    __shared__ __align__(16) bf sA[2][128][PADK];
    __shared__ __align__(16) bf sB[2][128][PADK];

    int tid = threadIdx.x;
    int wid = tid >> 5, lane = tid & 31;

    int z = blockIdx.z;
    A  += (long long)(z / hd) * zAo + (long long)(z % hd) * zAi;
    Bp += (long long)(z / hd) * zBo + (long long)(z % hd) * zBi;
    int m0 = blockIdx.y * 128, n0 = blockIdx.x * 128;

    int wm0 = (wid >> 2) * 64;
    int wn0 = (wid & 3) * 32;

    int ldRow0 = tid >> 2;            // 0..63
    int ldChunk = (tid & 3) * 8;      // bf16 col 0,8,16,24
    uint32_t sA0 = smem_u32(&sA[0][0][0]);
    uint32_t sB0 = smem_u32(&sB[0][0][0]);
    const uint32_t bufStride = 128 * PADK * 2;

    int q = lane >> 3, i8 = lane & 7;
    int aLaneRow = i8 + (q & 1) * 8;
    int aLaneCol = (q >> 1) * 8;
    int bLaneRow = i8;
    int bLaneCol = ((lane >> 3) & 1) * 8;

    const int aT[3] = {0, 0, 1}, bT[3] = {0, 1, 0};
    int kc = Kterm >> 5;
    int nc = 3 * kc;

    float acc[4][4][4] = {};

    // ---- issue chunk 0 loads (term 0, w 0: A and B cols coincide) ----
    {
        int col0 = ldChunk;
        #pragma unroll
        for (int u = 0; u < 2; u++) {
            int rr = ldRow0 + u * 64;
            cp16(sA0 + (rr * PADK + ldChunk) * 2,
                 A + (size_t)(m0 + rr) * ldA + col0);
            cp16(sB0 + (rr * PADK + ldChunk) * 2,
                 Bp + (size_t)(n0 + rr) * ldB + col0);
        }
        CP_COMMIT();
    }

    for (int ci = 0; ci < nc; ci++) {
        int cur = ci & 1;
        if (ci + 1 < nc) {
            int nxt = cur ^ 1;
            int term = (ci + 1) / kc, w = (ci + 1) % kc;
            int aCol = aT[term] * KtotA + w * 32 + ldChunk;
            int bCol = bT[term] * KtotB + w * 32 + ldChunk;
            #pragma unroll
            for (int u = 0; u < 2; u++) {
                int rr = ldRow0 + u * 64;
                cp16(sA0 + nxt * bufStride + (rr * PADK + ldChunk) * 2,
                     A + (size_t)(m0 + rr) * ldA + aCol);
                cp16(sB0 + nxt * bufStride + (rr * PADK + ldChunk) * 2,
                     Bp + (size_t)(n0 + rr) * ldB + bCol);
            }
            CP_COMMIT();
            CP_WAIT1();
        } else {
            CP_WAIT0();
        }
        __syncthreads();

        uint32_t aBase = sA0 + cur * bufStride;
        uint32_t bBase = sB0 + cur * bufStride;
        #pragma unroll
        for (int ks = 0; ks < 2; ks++) {
            int k0 = ks * 16;
            uint32_t af[4][4], bf2[4][2];
            #pragma unroll
            for (int mi = 0; mi < 4; mi++)
                ldsm4(af[mi], aBase +
                      ((wm0 + mi * 16 + aLaneRow) * PADK + k0 + aLaneCol) * 2);
            #pragma unroll
            for (int ni = 0; ni < 4; ni++)
                ldsm2(bf2[ni], bBase +
                      ((wn0 + ni * 8 + bLaneRow) * PADK + k0 + bLaneCol) * 2);
            #pragma unroll
            for (int mi = 0; mi < 4; mi++)
                #pragma unroll
                for (int ni = 0; ni < 4; ni++)
                    mma16816(acc[mi][ni], af[mi], bf2[ni]);
        }
        __syncthreads();
    }

    // ---- epilogue ----
    int lr = lane >> 2;
    int lc = (lane & 3) * 2;
    #pragma unroll
    for (int mi = 0; mi < 4; mi++) {
        #pragma unroll
        for (int s = 0; s < 2; s++) {
            int m = m0 + wm0 + mi * 16 + lr + s * 8;
            #pragma unroll
            for (int ni = 0; ni < 4; ni++) {
                int n = n0 + wn0 + ni * 8 + lc;
                float v0 = acc[mi][ni][2 * s + 0] * alpha;
                float v1 = acc[mi][ni][2 * s + 1] * alpha;
                if (bias) { v0 += bias[n]; v1 += bias[n + 1]; }
                if (doRelu) { v0 = fmaxf(v0, 0.f); v1 = fmaxf(v1, 0.f); }
                if (res) {
                    const float2 r2 = *(const float2*)(res + (long long)z * zR
                                       + (size_t)m * ldc + n);
                    v0 += r2.x; v1 += r2.y;
                }
                if (outMode != 1) {
                    float2 o2 = make_float2(v0, v1);
                    *(float2*)(Cp + (long long)z * zC + (size_t)m * ldc + n) = o2;
                }
                if (outMode >= 1) {
                    bf* op = Os + (size_t)m * ldOs + n;
                    *(uint32_t*)op = pk2(v0, v1);
                    *(uint32_t*)(op + KtotO) = pk2(rezf(v0), rezf(v1));
                }
            }
        }
    }
}

// ===========================================================================
// Temporal causal attention (fp32 QKV packed [row][768], split-bf16 out).
// Block per (b,h). q pre-scaled via folded weights.
// ===========================================================================
__global__ __launch_bounds__(256) void attn_t_kernel(
    const float* __restrict__ qkv, bf* __restrict__ op)
{
    extern __shared__ float smem[];
    float4* Ks = (float4*)smem;
    float4* Vs = (float4*)(smem + Tn * 32);

    int bh = blockIdx.x;
    int b = bh / Hn, h = bh % Hn;
    const size_t base = (size_t)b * Tn * 768 + (size_t)h * 32;

    for (int i = threadIdx.x; i < Tn * 8; i += 256) {
        int s = i >> 3, d4 = i & 7;
        Ks[i] = *(const float4*)(qkv + base + (size_t)s * 768 + 256 + d4 * 4);
        Vs[i] = *(const float4*)(qkv + base + (size_t)s * 768 + 512 + d4 * 4);
    }
    __syncthreads();

    int warp = threadIdx.x >> 5;
    int lane = threadIdx.x & 31;

    for (int pass = 0; pass < 2; pass++) {
        int qt = (pass == 0) ? warp : (15 - warp);
        int t = qt * 32 + lane;

        float qr[32];
        #pragma unroll
        for (int d4 = 0; d4 < 8; d4++) {
            float4 qv = *(const float4*)(qkv + base + (size_t)t * 768 + d4 * 4);
            qr[d4*4+0] = qv.x; qr[d4*4+1] = qv.y; qr[d4*4+2] = qv.z; qr[d4*4+3] = qv.w;
        }

        float m = -INFINITY, l = 0.f;
        float oa[32];
        #pragma unroll
        for (int d = 0; d < 32; d++) oa[d] = 0.f;

        for (int st = 0; st <= qt; st++) {
            float scr[32];
            float mx = -INFINITY;
            #pragma unroll
            for (int sk = 0; sk < 32; sk++) {
                int s = st * 32 + sk;
                float a = 0.f;
                #pragma unroll
                for (int d4 = 0; d4 < 8; d4++) {
                    float4 kk = Ks[s * 8 + d4];
                    a += qr[d4*4+0]*kk.x + qr[d4*4+1]*kk.y
                       + qr[d4*4+2]*kk.z + qr[d4*4+3]*kk.w;
                }
                if (st == qt && sk > lane) a = -INFINITY;
                scr[sk] = a;
                mx = fmaxf(mx, a);
            }
            float mn = fmaxf(m, mx);
            float f = expf(m - mn);
            l *= f;
            #pragma unroll
            for (int d = 0; d < 32; d++) oa[d] *= f;

            #pragma unroll
            for (int sk = 0; sk < 32; sk++) {
                float p = expf(scr[sk] - mn);
                l += p;
                int s = st * 32 + sk;
                #pragma unroll
                for (int d4 = 0; d4 < 8; d4++) {
                    float4 vv = Vs[s * 8 + d4];
                    oa[d4*4+0] += p*vv.x; oa[d4*4+1] += p*vv.y;
                    oa[d4*4+2] += p*vv.z; oa[d4*4+3] += p*vv.w;
                }
            }
            m = mn;
        }

        float inv = 1.f / l;
        size_t rowp = ((size_t)b * Tn + t) * 512 + h * 32;
        #pragma unroll
        for (int g = 0; g < 4; g++) {
            float w0 = oa[g*8+0]*inv, w1 = oa[g*8+1]*inv, w2 = oa[g*8+2]*inv,
                  w3 = oa[g*8+3]*inv, w4 = oa[g*8+4]*inv, w5 = oa[g*8+5]*inv,
                  w6 = oa[g*8+6]*inv, w7 = oa[g*8+7]*inv;
            uint4 h4, l4;
            h4.x = pk2(w0, w1); h4.y = pk2(w2, w3);
            h4.z = pk2(w4, w5); h4.w = pk2(w6, w7);
            l4.x = pk2(rezf(w0), rezf(w1)); l4.y = pk2(rezf(w2), rezf(w3));
            l4.z = pk2(rezf(w4), rezf(w5)); l4.w = pk2(rezf(w6), rezf(w7));
            *(uint4*)(op + rowp + g * 8) = h4;
            *(uint4*)(op + rowp + 256 + g * 8) = l4;
        }
    }
}

// ===========================================================================
// Spatial softmax + head-mean: warp per (b,c,h); block per (b,c).
// sc [B,H,C,C] -> sw fp32 [B,C,C] + split bf16
// ===========================================================================
__global__ __launch_bounds__(256) void softmax_mean_kernel(
    const float* __restrict__ scp, float* __restrict__ sw,
    bf* __restrict__ swp)
{
    __shared__ float smv[8][256];
    int bc = blockIdx.x;
    int b = bc >> 8, c = bc & 255;
    int tid = threadIdx.x, w = tid >> 5, lane = tid & 31;

    const float* row = scp + (((size_t)(b * 8 + w) * 256) + c) * 256;
    float v[8];
    float mx = -INFINITY;
    #pragma unroll
    for (int i = 0; i < 8; i++) { v[i] = row[lane + 32 * i]; mx = fmaxf(mx, v[i]); }
    #pragma unroll
    for (int o = 16; o; o >>= 1) mx = fmaxf(mx, __shfl_xor_sync(~0u, mx, o));
    float s = 0.f;
    #pragma unroll
    for (int i = 0; i < 8; i++) { v[i] = expf(v[i] - mx); s += v[i]; }
    #pragma unroll
    for (int o = 16; o; o >>= 1) s += __shfl_xor_sync(~0u, s, o);
    float inv = 1.f / (8.f * s);
    #pragma unroll
    for (int i = 0; i < 8; i++) smv[w][lane + 32 * i] = v[i] * inv;
    __syncthreads();

    float val = smv[0][tid];
    #pragma unroll
    for (int h = 1; h < 8; h++) val += smv[h][tid];
    sw[(size_t)bc * 256 + tid] = val;
    bf h16 = __float2bfloat16(val);
    swp[(size_t)bc * 512 + tid] = h16;
    swp[(size_t)bc * 512 + 256 + tid] =
        __float2bfloat16(val - __bfloat162float(h16));
}

// ===========================================================================
// Host side
// ===========================================================================
typedef long long ll;

static void g_tc(const bf* A, int ldA, int KA, const bf* B, int ldB, int KB,
                 int Kterm, float* C, int ldc, bf* Os, int ldOs, int KO,
                 const float* bias, const float* res, float alpha, int relu,
                 int mode, int M, int N, int nz = 1,
                 ll zAo = 0, ll zAi = 0, ll zBo = 0, ll zBi = 0,
                 ll zC = 0, ll zR = 0, int hd = 1)
{
    dim3 g(N / 128, M / 128, nz);
    gemm_mma<<<g, 256>>>(A, ldA, KA, B, ldB, KB, Kterm, C, ldc,
                         Os, ldOs, KO, bias, res, alpha, relu, mode,
                         zAo, zAi, zBo, zBi, zC, zR, hd);
}

extern "C" void kernel_launch(void* const* d_in, const int* in_sizes, int n_in,
                              void* d_out, int out_size)
{
    const float* x_T     = (const float*)d_in[0];
    const float* x_S     = (const float*)d_in[1];
    const float* Wq_t    = (const float*)d_in[2];
    const float* Wk_t    = (const float*)d_in[3];
    const float* Wv_t    = (const float*)d_in[4];
    const float* Wo      = (const float*)d_in[5];
    const float* Wq_s    = (const float*)d_in[6];
    const float* Wk_s    = (const float*)d_in[7];
    const float* ff1_w1  = (const float*)d_in[8];
    const float* ff1_b1  = (const float*)d_in[9];
    const float* ff1_w2  = (const float*)d_in[10];
    const float* ff1_b2  = (const float*)d_in[11];
    const float* ff2_w1  = (const float*)d_in[12];
    const float* ff2_b1  = (const float*)d_in[13];
    const float* ff2_w2  = (const float*)d_in[14];
    const float* ff2_b2  = (const float*)d_in[15];
    const float* t_ln1_w = (const float*)d_in[16];
    const float* t_ln1_b = (const float*)d_in[17];
    const float* t_ln2_w = (const float*)d_in[18];
    const float* t_ln2_b = (const float*)d_in[19];
    const float* s_ln1_w = (const float*)d_in[20];
    const float* s_ln1_b = (const float*)d_in[21];
    const float* fus_ln_w = (const float*)d_in[22];
    const float* fus_ln_b = (const float*)d_in[23];

    float* S = nullptr;
    cudaGetSymbolAddress((void**)&S, g_f32);
    bf* Bm = nullptr;
    cudaGetSymbolAddress((void**)&Bm, g_bf);

    float* out = (float*)d_out;
    float* sw  = out + SZ_BTC;

    cudaFuncSetAttribute(attn_t_kernel,
                         cudaFuncAttributeMaxDynamicSharedMemorySize, 131072);

    const float iq = 0.17677669529663687f;  // 1/sqrt(32)

    // ---- fused weight conversion (iq folded into Wq_t) ----
    CvtArgs ca;
    const float* srcs[10] = {Wq_t, Wk_t, Wv_t, Wo, Wq_s, Wk_s,
                             ff1_w1, ff1_w2, ff2_w1, ff2_w2};
    ll dsts[10] = {BWQKV, BWQKV + 256*512, BWQKV + 512*512, BWO,
                   BWQKS, BWQKS + 512*1024, BW11, BW12, BW21, BW22};
    int Ks[10] = {256, 256, 256, 256, 512, 512, 256, 1024, 256, 1024};
    float scl[10] = {iq, 1.f, 1.f, 1.f, 1.f, 1.f, 1.f, 1.f, 1.f, 1.f};
    int blks[10] = {256, 256, 256, 256, 1024, 1024, 1024, 1024, 1024, 1024};
    int acc = 0;
    for (int i = 0; i < 10; i++) {
        ca.src[i] = srcs[i]; ca.dst[i] = dsts[i]; ca.K[i] = Ks[i];
        ca.scale[i] = scl[i]; ca.bStart[i] = acc; acc += blks[i];
    }
    ca.bStart[10] = acc;
    cvt_all<<<acc, 256>>>(ca, Bm);

    // ---- temporal branch ----
    ln_split_warp<8><<<1024, 256>>>(x_T, t_ln1_w, t_ln1_b, Bm + BH1);
    // fused QKV: N=768 (iq folded into Wq section)
    g_tc(Bm + BH1, 512, 256, Bm + BWQKV, 512, 256, 256,
         S + OFF_QKV, 768, nullptr, 0, 0, nullptr, nullptr, 1.f, 0, 0,
         8192, 768);
    attn_t_kernel<<<Bn * Hn, 256, 131072>>>(S + OFF_QKV, Bm + BO);
    g_tc(Bm + BO, 512, 256, Bm + BWO, 512, 256, 256,
         S + OFF_X, Cn, nullptr, 0, 0, nullptr, x_T, 1.f, 0, 0, 8192, 256);
    ln_split_warp<8><<<1024, 256>>>(S + OFF_X, t_ln2_w, t_ln2_b, Bm + BH2);
    g_tc(Bm + BH2, 512, 256, Bm + BW11, 512, 256, 256,
         nullptr, 0, Bm + BFFH, 2048, 1024, ff1_b1, nullptr, 1.f, 1, 1,
         8192, 1024);
    g_tc(Bm + BFFH, 2048, 1024, Bm + BW12, 2048, 1024, 1024,
         S + OFF_TOUT, Cn, Bm + BTOUT, 512, 256, ff1_b2, S + OFF_X,
         1.f, 0, 2, 8192, 256);

    // ---- spatial branch ----
    ln_split_warp<16><<<512, 256>>>(x_S, s_ln1_w, s_ln1_b, Bm + BHS);
    // fused qs|ks: N=1024 -> BQKS [4096][2048] (hi: qs(512)|ks(512), lo at +1024)
    g_tc(Bm + BHS, 1024, 512, Bm + BWQKS, 1024, 512, 512,
         nullptr, 0, Bm + BQKS, 2048, 1024, nullptr, nullptr, 1.f, 0, 1,
         4096, 1024);
    // sc[b,h] = 0.125 * qs_bh @ ks_bh^T  (z = b*H + h)
    g_tc(Bm + BQKS, 2048, 1024, Bm + BQKS + 512, 2048, 1024, 64,
         S + OFF_SC, Cn, nullptr, 0, 0, nullptr, nullptr, 0.125f, 0, 0,
         256, 256, Bn * Hn,
         (ll)256 * 2048, 64, (ll)256 * 2048, 64,
         (ll)Cn * Cn, 0, Hn);
    softmax_mean_kernel<<<Bn * Cn, 256>>>(S + OFF_SC, sw, Bm + BSW);

    // ---- fusion: x2 = tout + tout @ sw^T  (z = b) ----
    g_tc(Bm + BTOUT, 512, 256, Bm + BSW, 512, 256, 256,
         S + OFF_X2, Cn, nullptr, 0, 0, nullptr, S + OFF_TOUT, 1.f, 0, 0,
         512, 256, Bn,
         (ll)512 * 512, 0, (ll)256 * 512, 0,
         (ll)512 * 256, (ll)512 * 256, 1);

    // ---- FFN2 -> out ----
    ln_split_warp<8><<<1024, 256>>>(S + OFF_X2, fus_ln_w, fus_ln_b, Bm + BH3);
    g_tc(Bm + BH3, 512, 256, Bm + BW21, 512, 256, 256,
         nullptr, 0, Bm + BFFH, 2048, 1024, ff2_b1, nullptr, 1.f, 1, 1,
         8192, 1024);
    g_tc(Bm + BFFH, 2048, 1024, Bm + BW22, 2048, 1024, 1024,
         out, Cn, nullptr, 0, 0, ff2_b2, S + OFF_X2, 1.f, 0, 0, 8192, 256);
}